// round 17
// baseline (speedup 1.0000x reference)
#include <cuda_runtime.h>
#include <cuda_bf16.h>
#include <math.h>
#include <stdint.h>

// Problem dims
#define BB 32
#define SS 2048
#define CC 1536
#define NN 200
#define KSEL 128
#define NCAND 160             // candidate pool per batch (32-rank margin)
#define CPB 40                // candidates per exact block (4 blocks/batch)
#define TOT (BB * SS)         // 65536 tokens

#define NPAD 208              // class dim: 7/7/6/6 n-tiles across 4 N-warps
#define NCH16 96              // K chunks of 16
#define NCH64 24              // K chunks of 64
#define WCH1 (NPAD * 8)       // u32 per k16 chunk of swizzled W = 1664

// Scratch (no cudaMalloc allowed)
__device__ float g_logits[(size_t)NN * TOT];   // [n][token], 52.4 MB
__device__ float g_lse[TOT];                   // per-token logsumexp
__device__ float g_msum[BB * NN];              // per-(b,n) logit sums (atomic)
__device__ int   g_maxid[BB];
__device__ int   g_cand[BB * NCAND];           // candidate token indices
__device__ float g_cscore[BB * NCAND];         // exact scores of candidates
__device__ int   g_topk[BB * KSEL];
__device__ __align__(16) uint32_t g_wswz[NCH16 * WCH1];

__device__ __forceinline__ uint32_t pack2bf(float a, float b) {
    __nv_bfloat162 p = __float22bfloat162_rn(make_float2(a, b));
    return *reinterpret_cast<uint32_t*>(&p);
}

// ---------------------------------------------------------------------------
// K-1: W -> bf16, fragment-swizzled in global (proven). Also zeroes g_msum.
// ---------------------------------------------------------------------------
__global__ void wconv_kernel(const float* __restrict__ W) {
    int i = blockIdx.x * blockDim.x + threadIdx.x;
    if (i < BB * NN) g_msum[i] = 0.f;
    if (i >= NCH16 * WCH1) return;
    int c = i / WCH1;
    int rem = i % WCH1;
    int n = rem >> 3, p = rem & 7;
    float v0 = 0.f, v1 = 0.f;
    if (n < NN) {
        int k = c * 16 + 2 * p;
        v0 = W[(size_t)n * CC + k];
        v1 = W[(size_t)n * CC + k + 1];
    }
    int w = (p & 3) * 2 + (p >> 2);
    g_wswz[c * WCH1 + n * 8 + w] = pack2bf(v0, v1);
}

// ---------------------------------------------------------------------------
// K2: APPROX logits GEMM — VERBATIM round-16 version (proven 501.8us).
// k64 chunks, 8 warps = 2(M) x 4(N) SMSP-balanced, NPAD 208, fused csum.
// ---------------------------------------------------------------------------
#define MMA_BF16(d, a, b0_, b1_)                                            \
    asm volatile(                                                           \
        "mma.sync.aligned.m16n8k16.row.col.f32.bf16.bf16.f32 "              \
        "{%0,%1,%2,%3}, {%4,%5,%6,%7}, {%8,%9}, {%0,%1,%2,%3};"             \
        : "+f"(d[0]), "+f"(d[1]), "+f"(d[2]), "+f"(d[3])                    \
        : "r"(a[0]), "r"(a[1]), "r"(a[2]), "r"(a[3]), "r"(b0_), "r"(b1_))

#define XS64 4096             // u32 per x stage: [4 half][128][8]
#define WS64 (4 * WCH1)       // u32 per W stage: [4 k16][208][8] = 6656
#define SMEMB ((2 * XS64 + 2 * WS64 + NPAD + 2 * 512) * 4)

__global__ __launch_bounds__(256, 1)
void score_mma_kernel(const float* __restrict__ x,
                      const float* __restrict__ bias) {
    extern __shared__ uint32_t sm[];
    uint32_t* xs = sm;                        // [2 buf][4 half][128][8]
    uint32_t* ws = sm + 2 * XS64;             // [2 buf][4 k16][208][8]
    float* bias_s = (float*)(ws + 2 * WS64);  // [208]
    float* p_mx = bias_s + NPAD;              // [128][4]
    float* p_se = p_mx + 512;

    int tid  = threadIdx.x;
    int warp = tid >> 5, lane = tid & 31;
    int gid  = lane >> 2, tig = lane & 3;
    int mw   = warp & 1;                      // SMSP-balanced mapping
    int nw   = warp >> 1;                     // nw 0..3
    int ntc   = (nw < 2) ? 7 : 6;             // n-tiles this warp
    int nbase = (nw < 2) ? nw * 56 : 112 + (nw - 2) * 48;
    int token0 = blockIdx.x * 128;            // 16 blocks per batch
    int b = token0 >> 11;

    for (int n = tid; n < NPAD; n += 256)
        bias_s[n] = (n < NN) ? __ldg(&bias[n]) : -1e30f;

    float acc[4][7][4];
    #pragma unroll
    for (int mt = 0; mt < 4; mt++)
        #pragma unroll
        for (int nt = 0; nt < 7; nt++)
            #pragma unroll
            for (int r = 0; r < 4; r++) acc[mt][nt][r] = 0.f;

    const float* xbase = x + (size_t)token0 * CC;

    int xrow = tid >> 3;            // 0..31; tasks at rows +0,+32,+64,+96
    int xp   = tid & 7;
    int xw   = (xp & 3) * 2 + (xp >> 2);
    float2 rx[4][2];                // [task][k16-half within sub]

    auto ldxs = [&](int c, int s) {
        #pragma unroll
        for (int t = 0; t < 4; t++) {
            const float* p = xbase + (size_t)(xrow + 32 * t) * CC
                           + c * 64 + s * 32 + 2 * xp;
            rx[t][0] = *(const float2*)p;
            rx[t][1] = *(const float2*)(p + 16);
        }
    };
    auto stxs = [&](int buf, int s) {
        uint32_t* base = xs + buf * XS64 + s * 2048;
        #pragma unroll
        for (int t = 0; t < 4; t++) {
            int r = xrow + 32 * t;
            base[0 * 1024 + r * 8 + xw] = pack2bf(rx[t][0].x, rx[t][0].y);
            base[1 * 1024 + r * 8 + xw] = pack2bf(rx[t][1].x, rx[t][1].y);
        }
    };
    auto cpW = [&](int c, int wb) {
        const uint4* src = (const uint4*)(g_wswz + (size_t)(4 * c) * WCH1);
        uint32_t dst = (uint32_t)__cvta_generic_to_shared(ws + wb * WS64);
        #pragma unroll
        for (int r = 0; r < 6; r++) {
            int e = tid + r * 256;
            asm volatile("cp.async.cg.shared.global [%0], [%1], 16;"
                         :: "r"(dst + e * 16), "l"(src + e));
        }
        if (tid < 128) {
            int e = tid + 1536;                // 1664 total
            asm volatile("cp.async.cg.shared.global [%0], [%1], 16;"
                         :: "r"(dst + e * 16), "l"(src + e));
        }
    };

    auto mma_half = [&](const uint32_t* xsb, const uint32_t* wsb, int h) {
        uint32_t af[4][4];
        #pragma unroll
        for (int mt = 0; mt < 4; mt++) {
            int row0 = mw * 64 + mt * 16 + gid;
            const uint32_t* pa = xsb + h * 1024 + row0 * 8 + tig * 2;
            uint2 t0 = *(const uint2*)pa;
            uint2 t1 = *(const uint2*)(pa + 64);
            af[mt][0] = t0.x;  af[mt][2] = t0.y;
            af[mt][1] = t1.x;  af[mt][3] = t1.y;
        }
        #pragma unroll
        for (int nt = 0; nt < 7; nt++) {
            if (nt >= ntc) break;
            int nrow = nbase + nt * 8 + gid;
            uint2 B0 = *(const uint2*)(wsb + h * WCH1 + nrow * 8 + tig * 2);
            MMA_BF16(acc[0][nt], af[0], B0.x, B0.y);
            MMA_BF16(acc[1][nt], af[1], B0.x, B0.y);
            MMA_BF16(acc[2][nt], af[2], B0.x, B0.y);
            MMA_BF16(acc[3][nt], af[3], B0.x, B0.y);
        }
    };

    cpW(0, 0); asm volatile("cp.async.commit_group;");
    ldxs(0, 0); stxs(0, 0);
    ldxs(0, 1); stxs(0, 1);
    ldxs(1, 0);
    asm volatile("cp.async.wait_group 0;");
    __syncthreads();

    for (int c = 0; c < NCH64; c++) {
        int buf = c & 1;
        const uint32_t* xsb = xs + buf * XS64;
        const uint32_t* wsb = ws + buf * WS64;

        if (c + 1 < NCH64) { cpW(c + 1, buf ^ 1);
                             asm volatile("cp.async.commit_group;"); }

        mma_half(xsb, wsb, 0);
        mma_half(xsb, wsb, 1);
        if (c + 1 < NCH64) { stxs(buf ^ 1, 0); ldxs(c + 1, 1); }
        mma_half(xsb, wsb, 2);
        mma_half(xsb, wsb, 3);
        if (c + 1 < NCH64) {
            stxs(buf ^ 1, 1);
            if (c + 2 < NCH64) ldxs(c + 2, 0);
            asm volatile("cp.async.wait_group 0;");
            __syncthreads();
        }
    }

    // ---- bias add + logit store (transposed [n][token]) + fused class sums
    #pragma unroll
    for (int nt = 0; nt < 7; nt++) {
        if (nt >= ntc) break;
        int n0 = nbase + nt * 8 + tig * 2;
        float b0 = bias_s[n0], b1 = bias_s[n0 + 1];
        #pragma unroll
        for (int mt = 0; mt < 4; mt++) {
            acc[mt][nt][0] += b0; acc[mt][nt][1] += b1;
            acc[mt][nt][2] += b0; acc[mt][nt][3] += b1;
        }
        if (n0 < NN) {
            #pragma unroll
            for (int mt = 0; mt < 4; mt++) {
                int r0 = token0 + mw * 64 + mt * 16 + gid;
                g_logits[(size_t)n0 * TOT + r0]           = acc[mt][nt][0];
                g_logits[(size_t)(n0 + 1) * TOT + r0]     = acc[mt][nt][1];
                g_logits[(size_t)n0 * TOT + r0 + 8]       = acc[mt][nt][2];
                g_logits[(size_t)(n0 + 1) * TOT + r0 + 8] = acc[mt][nt][3];
            }
        }

        float s0 = 0.f, s1 = 0.f;
        #pragma unroll
        for (int mt = 0; mt < 4; mt++) {
            s0 += acc[mt][nt][0] + acc[mt][nt][2];
            s1 += acc[mt][nt][1] + acc[mt][nt][3];
        }
        #pragma unroll
        for (int o = 4; o <= 16; o <<= 1) {
            s0 += __shfl_xor_sync(0xffffffffu, s0, o);
            s1 += __shfl_xor_sync(0xffffffffu, s1, o);
        }
        if (gid == 0 && n0 < NN) {
            atomicAdd(&g_msum[b * NN + n0], s0);
            if (n0 + 1 < NN) atomicAdd(&g_msum[b * NN + n0 + 1], s1);
        }
    }

    #pragma unroll
    for (int mt = 0; mt < 4; mt++) {
        #pragma unroll
        for (int half = 0; half < 2; half++) {
            float mx = -1e30f;
            #pragma unroll
            for (int nt = 0; nt < 7; nt++) {
                if (nt >= ntc) break;
                mx = fmaxf(mx, fmaxf(acc[mt][nt][2 * half],
                                     acc[mt][nt][2 * half + 1]));
            }
            mx = fmaxf(mx, __shfl_xor_sync(0xffffffffu, mx, 1));
            mx = fmaxf(mx, __shfl_xor_sync(0xffffffffu, mx, 2));

            float se = 0.f;
            #pragma unroll
            for (int nt = 0; nt < 7; nt++) {
                if (nt >= ntc) break;
                se += expf(acc[mt][nt][2 * half] - mx)
                    + expf(acc[mt][nt][2 * half + 1] - mx);
            }
            se += __shfl_xor_sync(0xffffffffu, se, 1);
            se += __shfl_xor_sync(0xffffffffu, se, 2);

            if (tig == 0) {
                int row = mw * 64 + mt * 16 + half * 8 + gid;
                p_mx[row * 4 + nw] = mx;
                p_se[row * 4 + nw] = se;
            }
        }
    }
    __syncthreads();

    if (tid < 128) {
        float m0 = p_mx[tid * 4 + 0], m1 = p_mx[tid * 4 + 1];
        float m2 = p_mx[tid * 4 + 2], m3 = p_mx[tid * 4 + 3];
        float M = fmaxf(fmaxf(m0, m1), fmaxf(m2, m3));
        float se = p_se[tid * 4 + 0] * expf(m0 - M)
                 + p_se[tid * 4 + 1] * expf(m1 - M)
                 + p_se[tid * 4 + 2] * expf(m2 - M)
                 + p_se[tid * 4 + 3] * expf(m3 - M);
        g_lse[token0 + tid] = M + logf(se);
    }
}

// ---------------------------------------------------------------------------
// K3: cand_kernel with fused per-batch argmax + bitonic top-160 (proven r16).
// ---------------------------------------------------------------------------
__global__ void cand_kernel() {
    __shared__ float s[SS];
    __shared__ int   si[SS];
    __shared__ float av[256];
    __shared__ int   ai[256];
    __shared__ int   id_s;
    int b = blockIdx.x;
    int t = threadIdx.x;

    if (t < 256) {
        av[t] = (t < NN) ? g_msum[b * NN + t] : -INFINITY;
        ai[t] = (t < NN) ? t : (1 << 30);
    }
    __syncthreads();
    for (int o = 128; o > 0; o >>= 1) {
        if (t < o) {
            float v2 = av[t + o]; int i2 = ai[t + o];
            float v1 = av[t];     int i1 = ai[t];
            if (v2 > v1 || (v2 == v1 && i2 < i1)) { av[t] = v2; ai[t] = i2; }
        }
        __syncthreads();
    }
    if (t == 0) { id_s = ai[0]; g_maxid[b] = ai[0]; }
    __syncthreads();
    int id = id_s;

    const float* lg = g_logits + (size_t)id * TOT + b * SS;
    const float* ls = g_lse + b * SS;
    for (int e = t; e < SS; e += blockDim.x) {
        s[e]  = lg[e] - ls[e];
        si[e] = e;
    }
    __syncthreads();
    for (int k = 2; k <= SS; k <<= 1) {
        for (int j = k >> 1; j > 0; j >>= 1) {
            for (int e = t; e < SS; e += blockDim.x) {
                int ixj = e ^ j;
                if (ixj > e) {
                    float a = s[e],  c = s[ixj];
                    int  a2 = si[e], c2 = si[ixj];
                    bool aBetter = (a > c) || (a == c && a2 < c2);
                    bool descHere = ((e & k) == 0);
                    bool doSwap = descHere ? !aBetter : aBetter;
                    if (doSwap) {
                        s[e] = c;  s[ixj] = a;
                        si[e] = c2; si[ixj] = a2;
                    }
                }
            }
            __syncthreads();
        }
    }
    for (int e = t; e < NCAND; e += blockDim.x)
        g_cand[b * NCAND + e] = si[e];
}

// ---------------------------------------------------------------------------
// K5: EXACT rescore v2 — 512 threads, grid 128 (1 block/SM, 16 warps/SM).
// tx = lane covers n = tx + 32*j (j<7); warp w owns rows: w<8 -> 3 rows
// (w*3), w>=8 -> 2 rows (24+(w-8)*2); SMSPs perfectly balanced (10 rows).
// Per-(token,class) fp32 chain BIT-IDENTICAL to proven kernel (same k16
// chunk order, same kk/fmaf sequence, same bias/LSE math).
// ---------------------------------------------------------------------------
__global__ __launch_bounds__(512, 1)
void exact_kernel(const float* __restrict__ x,
                  const float* __restrict__ W,
                  const float* __restrict__ bias) {
    __shared__ float x_s[16 * 41];    // [kk][m], m<40, stride 41
    __shared__ float w_s[16 * 224];   // [kk][n], stride 224 (n<224, pad 0)
    __shared__ int   cind[CPB];

    int tid = threadIdx.x;
    int lane = tid & 31;               // tx = lane
    int wrp  = tid >> 5;               // 0..15
    int nr   = (wrp < 8) ? 3 : 2;
    int base = (wrp < 8) ? wrp * 3 : 24 + (wrp - 8) * 2;
    int b  = blockIdx.x >> 2;          // 4 blocks per batch
    int c0 = (blockIdx.x & 3) * CPB;

    if (tid < CPB) cind[tid] = g_cand[b * NCAND + c0 + tid];
    // zero pad region n in [200,224) once (16 kk x 24 n = 384 elems)
    if (tid < 384) {
        int kk = tid / 24, n = 200 + tid % 24;
        w_s[kk * 224 + n] = 0.f;
    }
    __syncthreads();

    float acc[3][7];
    #pragma unroll
    for (int i = 0; i < 3; i++)
        #pragma unroll
        for (int j = 0; j < 7; j++) acc[i][j] = 0.f;

    const float* xb = x + (size_t)b * SS * CC;

    for (int k0 = 0; k0 < CC; k0 += 16) {
        // x tile: 40 x 16 = 640 elems
        #pragma unroll
        for (int r = 0; r < 2; r++) {
            int e = tid + r * 512;
            if (e < 640) {
                int m = e >> 4, kk = e & 15;
                x_s[kk * 41 + m] = xb[(size_t)cind[m] * CC + k0 + kk];
            }
        }
        // W tile: 200 x 16 = 3200 elems
        #pragma unroll
        for (int r = 0; r < 7; r++) {
            int e = tid + r * 512;
            if (e < 3200) {
                int n = e >> 4, kk = e & 15;
                w_s[kk * 224 + n] = __ldg(&W[(size_t)n * CC + k0 + kk]);
            }
        }
        __syncthreads();

        #pragma unroll
        for (int kk = 0; kk < 16; kk++) {
            float xv[3];
            #pragma unroll
            for (int i = 0; i < 3; i++)
                xv[i] = (i < nr) ? x_s[kk * 41 + base + i] : 0.f;
            #pragma unroll
            for (int j = 0; j < 7; j++) {
                float wv = w_s[kk * 224 + lane + 32 * j];
                #pragma unroll
                for (int i = 0; i < 3; i++)
                    if (i < nr) acc[i][j] = fmaf(xv[i], wv, acc[i][j]);
            }
        }
        __syncthreads();
    }

    int id = g_maxid[b];
    #pragma unroll
    for (int i = 0; i < 3; i++) {
        if (i >= nr) break;
        float mx = -1e30f;
        #pragma unroll
        for (int j = 0; j < 7; j++) {
            int n = lane + 32 * j;
            if (n < NN) {
                acc[i][j] += __ldg(&bias[n]);
                mx = fmaxf(mx, acc[i][j]);
            }
        }
        #pragma unroll
        for (int o = 16; o > 0; o >>= 1)
            mx = fmaxf(mx, __shfl_xor_sync(0xffffffffu, mx, o));

        float se = 0.f, lv = 0.f;
        #pragma unroll
        for (int j = 0; j < 7; j++) {
            int n = lane + 32 * j;
            if (n < NN) {
                se += expf(acc[i][j] - mx);
                if (n == id) lv = acc[i][j];
            }
        }
        #pragma unroll
        for (int o = 16; o > 0; o >>= 1) {
            se += __shfl_xor_sync(0xffffffffu, se, o);
            lv += __shfl_xor_sync(0xffffffffu, lv, o);
        }
        if (lane == 0)
            g_cscore[b * NCAND + c0 + base + i] = lv - mx - logf(se);
    }
}

// ---------------------------------------------------------------------------
// K6: per-batch sort of 160 candidates (padded to 256) by EXACT score.
// ---------------------------------------------------------------------------
__global__ void sort2_kernel() {
    __shared__ float s[256];
    __shared__ int   si[256];
    int b = blockIdx.x;
    int t = threadIdx.x;
    if (t < NCAND) {
        s[t]  = g_cscore[b * NCAND + t];
        si[t] = g_cand[b * NCAND + t];
    } else {
        s[t]  = -INFINITY;
        si[t] = 1 << 30;
    }
    __syncthreads();
    for (int k = 2; k <= 256; k <<= 1) {
        for (int j = k >> 1; j > 0; j >>= 1) {
            int ixj = t ^ j;
            if (ixj > t) {
                float a = s[t],  c = s[ixj];
                int  ai = si[t], ci = si[ixj];
                bool aBetter = (a > c) || (a == c && ai < ci);
                bool descHere = ((t & k) == 0);
                bool doSwap = descHere ? !aBetter : aBetter;
                if (doSwap) {
                    s[t] = c;  s[ixj] = a;
                    si[t] = ci; si[ixj] = ai;
                }
            }
            __syncthreads();
        }
    }
    if (t < KSEL) g_topk[b * KSEL + t] = si[t];
}

// ---------------------------------------------------------------------------
// K7: gather out[b, j, :] = x[b, topk[b][j], :]  (float4 vectorized)
// ---------------------------------------------------------------------------
__global__ void gather_kernel(const float* __restrict__ x,
                              float* __restrict__ out) {
    int row = blockIdx.x;
    int b = row >> 7, j = row & (KSEL - 1);
    int sidx = g_topk[b * KSEL + j];
    const float4* src = (const float4*)(x + ((size_t)b * SS + sidx) * CC);
    float4* dst = (float4*)(out + (size_t)row * CC);
    for (int c = threadIdx.x; c < CC / 4; c += blockDim.x) dst[c] = src[c];
}

// ---------------------------------------------------------------------------
extern "C" void kernel_launch(void* const* d_in, const int* in_sizes, int n_in,
                              void* d_out, int out_size) {
    const float* x    = (const float*)d_in[0];   // [32, 2048, 1536]
    const float* W    = (const float*)d_in[1];   // [200, 1536]
    const float* bias = (const float*)d_in[2];   // [200]
    float* out = (float*)d_out;                  // [32, 128, 1536]

    cudaFuncSetAttribute(score_mma_kernel,
                         cudaFuncAttributeMaxDynamicSharedMemorySize, SMEMB);

    wconv_kernel<<<(NCH16 * WCH1 + 255) / 256, 256>>>(W);
    score_mma_kernel<<<TOT / 128, 256, SMEMB>>>(x, bias);
    cand_kernel<<<BB, 1024>>>();
    exact_kernel<<<BB * (NCAND / CPB), 512>>>(x, W, bias);
    sort2_kernel<<<BB, 256>>>();
    gather_kernel<<<BB * KSEL, 256>>>(x, out);
}